// round 14
// baseline (speedup 1.0000x reference)
#include <cuda_runtime.h>
#include <cuda_bf16.h>

// Problem constants: shape (2,3,512,512) fp32, KS=5, PAD=2, ALPHA1=0.1, ALPHA2=1.5, EPS=1e-8
#define HH 512
#define WW 512
#define NPLANE 6
#define NPIX (HH * WW)
#define NTOT (NPLANE * NPIX)           // 1,572,864 per tensor

// bilat block: 32x8 threads, each thread computes 2 pixels in y -> 32x16 tile
#define GXB 16                          // 512/32
#define GYB 32                          // 512/16
#define NBLOCKS (GXB * GYB * NPLANE)    // 3072

// __device__ globals are zero-initialized at module load; bilat's last block
// resets them after use, so every graph replay starts clean with NO init kernel.
__device__ int          g_negflag[2];
__device__ unsigned int g_count;
__device__ float        g_partials[NBLOCKS];

#define L2E  1.4426950408889634f
#define NEGK (-5.0f * L2E)             // -(1/(2*alpha1)) * log2(e)

typedef unsigned long long u64;

// ---------------------------------------------------------------------------
// packed fp32x2 helpers (one wide op = both tensors; issue-slot saver)
__device__ __forceinline__ u64 pk2(float lo, float hi) {
    u64 r; asm("mov.b64 %0, {%1, %2};" : "=l"(r) : "f"(lo), "f"(hi)); return r;
}
__device__ __forceinline__ void upk2(u64 v, float& lo, float& hi) {
    asm("mov.b64 {%0, %1}, %2;" : "=f"(lo), "=f"(hi) : "l"(v));
}
__device__ __forceinline__ u64 mul2(u64 a, u64 b) {
    u64 r; asm("mul.rn.f32x2 %0, %1, %2;" : "=l"(r) : "l"(a), "l"(b)); return r;
}
__device__ __forceinline__ u64 fma2(u64 a, u64 b, u64 c) {
    u64 r; asm("fma.rn.f32x2 %0, %1, %2, %3;" : "=l"(r) : "l"(a), "l"(b), "l"(c)); return r;
}
__device__ __forceinline__ float ex2f(float x) {
    float y; asm("ex2.approx.ftz.f32 %0, %1;" : "=f"(y) : "f"(x)); return y;
}

__device__ __forceinline__ int reflect(int i) {
    // jnp.pad mode='reflect', pad=2, dim=512:  -1->1, -2->2, 512->510, 513->509
    return (i < 0) ? -i : ((i >= HH) ? (2 * HH - 2 - i) : i);
}

// spatial gaussian e^{-s/3}; exact same result as reference since the
// per-window constant factor exp2(-NEGK*c^2) is common to ALL taps (self tap
// included) and cancels in sum(wp)/sum(w)
__device__ __forceinline__ constexpr float spatialS(int s) {
    return (s == 0) ? 1.0f
         : (s == 1) ? 0.71653131f
         : (s == 2) ? 0.51341712f
         : (s == 4) ? 0.26359714f
         : (s == 5) ? 0.18887560f
         :            0.06948345f;
}

// ---------------------------------------------------------------------------
// "img.min() < 0" <=> any element < 0.  Plain full scan (no same-address polling).
__global__ __launch_bounds__(256) void flag_kernel(const float4* __restrict__ a,
                                                   const float4* __restrict__ b,
                                                   int n4) {
    int fa = 0, fb = 0;
    const int stride = gridDim.x * blockDim.x;
    for (int i = blockIdx.x * blockDim.x + threadIdx.x; i < n4; i += stride) {
        float4 va = a[i];
        float4 vb = b[i];
        fa |= (va.x < 0.f) | (va.y < 0.f) | (va.z < 0.f) | (va.w < 0.f);
        fb |= (vb.x < 0.f) | (vb.y < 0.f) | (vb.z < 0.f) | (vb.w < 0.f);
    }
    if (__any_sync(0xffffffffu, fa) && ((threadIdx.x & 31) == 0)) g_negflag[0] = 1;
    if (__any_sync(0xffffffffu, fb) && ((threadIdx.x & 31) == 0)) g_negflag[1] = 1;
}

// ---------------------------------------------------------------------------
// Fused bilateral(A), bilateral(B), |diff| partial sum, last-block final
// reduction + state reset.  f32x2 packed math, coarsen-2 in y.  Row-batched
// structure: per dy row, all 5 args for one window are computed, then a
// 10-deep back-to-back EX2 burst fires, then that window accumulates --
// deep independent MUFU work per warp so EX2 throughput saturates even at
// moderate occupancy.
__global__ __launch_bounds__(256, 5) void bilat_kernel(const float* __restrict__ A,
                                                       const float* __restrict__ B,
                                                       float* __restrict__ out) {
    __shared__ float2 sT[20][36];       // .x = A value, .y = B value (5.76 KB)
    __shared__ float  swarp[8];
    __shared__ int    s_islast;

    const int tx  = threadIdx.x;        // 0..31
    const int ty  = threadIdx.y;        // 0..7
    const int tid = ty * 32 + tx;
    const int x0  = blockIdx.x * 32;
    const int y0  = blockIdx.y * 16;
    const int plane = blockIdx.z;

    const float sclA = g_negflag[0] ? 0.5f : 1.0f;
    const float bseA = g_negflag[0] ? 0.5f : 0.0f;
    const float sclB = g_negflag[1] ? 0.5f : 1.0f;
    const float bseB = g_negflag[1] ? 0.5f : 0.0f;

    const float* __restrict__ Ap = A + plane * NPIX;
    const float* __restrict__ Bp = B + plane * NPIX;

    // cooperative halo load: 20x36 tile (reflect at borders), normalized at load
    for (int idx = tid; idx < 20 * 36; idx += 256) {
        int r  = idx / 36;
        int c  = idx - r * 36;
        int gy = reflect(y0 - 2 + r);
        int gx = reflect(x0 - 2 + c);
        int g  = gy * WW + gx;
        sT[r][c] = make_float2(fmaf(__ldg(Ap + g), sclA, bseA),
                               fmaf(__ldg(Bp + g), sclB, bseB));
    }
    __syncthreads();

    const u64* __restrict__ sTu = reinterpret_cast<const u64*>(&sT[0][0]);

    const u64 NEGK2 = pk2(NEGK, NEGK);

    // 2 output pixels per thread: tile rows 2ty, 2ty+1 (smem center rows +2)
    const int base = ty * 2 * 36 + tx;  // &sT[2ty][tx] in u64 units

    u64 K10, K11, ws0, ws1, ac0, ac1;
    {
        const u64 M2NEGK = pk2(-2.0f * NEGK, -2.0f * NEGK);
        K10 = mul2(sTu[base + 2 * 36 + 2], M2NEGK);
        K11 = mul2(sTu[base + 3 * 36 + 2], M2NEGK);
        ws0 = ws1 = ac0 = ac1 = pk2(0.f, 0.f);
    }

#pragma unroll
    for (int dy = 0; dy < 6; dy++) {           // smem rows 2ty+dy
        const bool has0 = (dy <= 4);           // window o=0 uses rel=dy
        const bool has1 = (dy >= 1);           // window o=1 uses rel=dy-1

        // load the 5-wide row once; q = NEGK*p^2 shared by both windows
        u64 p[5], q[5];
#pragma unroll
        for (int dx = 0; dx < 5; dx++) {
            p[dx] = sTu[base + dy * 36 + dx];      // one LDS.64, both tensors
            q[dx] = mul2(mul2(p[dx], p[dx]), NEGK2);
        }

        if (has0) {
            // args for all 5 dx, then a 10-deep EX2 burst, then accumulate
            float wl[5], wh[5];
#pragma unroll
            for (int dx = 0; dx < 5; dx++) {
                float al, ah;
                upk2(fma2(p[dx], K10, q[dx]), al, ah);
                wl[dx] = ex2f(al);
                wh[dx] = ex2f(ah);
            }
#pragma unroll
            for (int dx = 0; dx < 5; dx++) {
                const int s = (dy - 2) * (dy - 2) + (dx - 2) * (dx - 2);
                const float sp = spatialS(s);
                const u64 S = pk2(sp, sp);
                u64 w = pk2(wl[dx], wh[dx]);
                ws0 = fma2(w, S, ws0);
                ac0 = fma2(mul2(w, p[dx]), S, ac0);
            }
        }
        if (has1) {
            float wl[5], wh[5];
#pragma unroll
            for (int dx = 0; dx < 5; dx++) {
                float al, ah;
                upk2(fma2(p[dx], K11, q[dx]), al, ah);
                wl[dx] = ex2f(al);
                wh[dx] = ex2f(ah);
            }
#pragma unroll
            for (int dx = 0; dx < 5; dx++) {
                const int s = (dy - 3) * (dy - 3) + (dx - 2) * (dx - 2);
                const float sp = spatialS(s);
                const u64 S = pk2(sp, sp);
                u64 w = pk2(wl[dx], wh[dx]);
                ws1 = fma2(w, S, ws1);
                ac1 = fma2(mul2(w, p[dx]), S, ac1);
            }
        }
    }

    // common factor exp2(-NEGK*c^2) cancels in the ratio; EPS is a fp32 no-op
    // in the reference (wsum >= 1 there), so plain divide is exact.
    float v;
    {
        float wsa, wsb, aca, acb;
        upk2(ws0, wsa, wsb);
        upk2(ac0, aca, acb);
        v = fabsf(__fdividef(aca, wsa) - __fdividef(acb, wsb));
        upk2(ws1, wsa, wsb);
        upk2(ac1, aca, acb);
        v += fabsf(__fdividef(aca, wsa) - __fdividef(acb, wsb));
    }

    // deterministic block reduction
#pragma unroll
    for (int o = 16; o > 0; o >>= 1) v += __shfl_down_sync(0xffffffffu, v, o);
    if ((tid & 31) == 0) swarp[tid >> 5] = v;
    __syncthreads();
    if (tid == 0) {
        float t = 0.f;
#pragma unroll
        for (int w = 0; w < 8; w++) t += swarp[w];
        int bidx = (blockIdx.z * gridDim.y + blockIdx.y) * gridDim.x + blockIdx.x;
        g_partials[bidx] = t;
        __threadfence();
        unsigned int done = atomicAdd(&g_count, 1u);
        s_islast = (done == (unsigned int)(NBLOCKS - 1));
    }
    __syncthreads();

    // last block: deterministic final reduction over L2-hot partials, then
    // reset device state so the next graph replay starts clean.
    if (s_islast) {
        float s = 0.f;
#pragma unroll
        for (int i = 0; i < NBLOCKS / 256; i++)     // 12 scalars per thread
            s += g_partials[tid + i * 256];
#pragma unroll
        for (int o = 16; o > 0; o >>= 1) s += __shfl_down_sync(0xffffffffu, s, o);
        if ((tid & 31) == 0) swarp[tid >> 5] = s;
        __syncthreads();
        if (tid == 0) {
            float t = 0.f;
#pragma unroll
            for (int w = 0; w < 8; w++) t += swarp[w];
            out[0] = t * (1.0f / (float)NTOT);
            g_negflag[0] = 0;              // self-clean for next replay
            g_negflag[1] = 0;
            g_count      = 0;
        }
    }
}

// ---------------------------------------------------------------------------
extern "C" void kernel_launch(void* const* d_in, const int* in_sizes, int n_in,
                              void* d_out, int out_size) {
    const float* A = (const float*)d_in[0];   // output
    const float* B = (const float*)d_in[1];   // target
    float* out = (float*)d_out;

    flag_kernel<<<256, 256>>>((const float4*)A, (const float4*)B, NTOT / 4);

    dim3 grid(GXB, GYB, NPLANE);
    dim3 block(32, 8);
    bilat_kernel<<<grid, block>>>(A, B, out);
}